// round 2
// baseline (speedup 1.0000x reference)
#include <cuda_runtime.h>
#include <cstdint>

// MaxUnpooling2D: updates [16,64,64,256] f32, mask int32 (flat index over
// (oH,oW,C) per batch), output [16,128,128,256] f32.
//
// Input-centric expansion: each thread owns one (b,h,w) cell and a 4-channel
// quad. It reads the mask/update quad once and writes the 4 output positions
// of the 2x2 window (match -> value, else 0). Every output element is written
// exactly once, so no zero-init pass is needed.
//
// All traffic is touch-once -> streaming cache hints (__ldcs / __stcs) so the
// 396 MB of single-use data doesn't thrash L2.

#define B_  16
#define H_  64
#define W_  64
#define C_  256
#define OH_ 128
#define OW_ 128
#define C4_ (C_ / 4)                         // 64 float4 quads per pixel
#define NTHREADS_TOTAL (B_ * H_ * W_ * C4_)  // 4,194,304

__global__ __launch_bounds__(256)
void maxunpool2d_kernel(const float4* __restrict__ upd4,
                        const int4*  __restrict__ msk4,
                        float4* __restrict__ out4)
{
    const int t = blockIdx.x * blockDim.x + threadIdx.x;

    // Decompose t -> (b, h, w, c4). All dims are powers of two.
    const int c4 = t & (C4_ - 1);
    int r = t >> 6;            // log2(C4_) = 6
    const int w = r & (W_ - 1);
    r >>= 6;                   // log2(W_) = 6
    const int h = r & (H_ - 1);
    const int b = r >> 6;      // log2(H_) = 6

    // Streaming loads: data is touch-once, evict-first.
    const float4 u = __ldcs(&upd4[t]);
    const int4   m = __ldcs(&msk4[t]);

    const int oy = h << 1;
    const int ox = w << 1;
    const int cbase = c4 << 2;               // element channel of .x component

    // Output float4 index for window position (dy,dx):
    //   ((b*OH + oy+dy)*OW + ox+dx)*C4 + c4
    const int obase = ((b * OH_ + oy) * OW_ + ox) * C4_ + c4;

    #pragma unroll
    for (int dy = 0; dy < 2; ++dy) {
        #pragma unroll
        for (int dx = 0; dx < 2; ++dx) {
            // Flat mask target for element (oy+dy, ox+dx, cbase+k):
            const int tb = ((oy + dy) * OW_ + (ox + dx)) * C_ + cbase;
            float4 o;
            o.x = (m.x == tb + 0) ? u.x : 0.0f;
            o.y = (m.y == tb + 1) ? u.y : 0.0f;
            o.z = (m.z == tb + 2) ? u.z : 0.0f;
            o.w = (m.w == tb + 3) ? u.w : 0.0f;
            __stcs(&out4[obase + dy * (OW_ * C4_) + dx * C4_], o);
        }
    }
}

extern "C" void kernel_launch(void* const* d_in, const int* in_sizes, int n_in,
                              void* d_out, int out_size)
{
    const float4* upd4 = (const float4*)d_in[0];
    const int4*   msk4 = (const int4*)d_in[1];
    float4*       out4 = (float4*)d_out;

    const int threads = 256;
    const int blocks  = NTHREADS_TOTAL / threads;  // 16384, exact coverage
    maxunpool2d_kernel<<<blocks, threads>>>(upd4, msk4, out4);
}